// round 16
// baseline (speedup 1.0000x reference)
#include <cuda_runtime.h>
#include <cuda_fp8.h>
#include <cuda_fp16.h>
#include <cstdint>
#include <cstring>

// ===================== problem constants =====================
#define M_DIM 8192
#define K_DIM 4096
#define N_DIM 4096
#define KBC   (K_DIM / 128)              // 32 K-chunks of 128
#define NBC   (N_DIM / 128)              // 32 weight-block columns

// ===================== scratch (device globals, no malloc) =====================
__device__ uint8_t g_qx[(size_t)M_DIM * K_DIM];   // fp8 e4m3 activations
__device__ float   g_sx[M_DIM * KBC];             // act scales [M, K/128]
__device__ uint8_t g_qw[(size_t)N_DIM * K_DIM];   // fp8 e4m3 weights
__device__ float   g_sw[NBC * KBC];               // weight scales [N/128, K/128]

// ===================== helpers =====================
__device__ __forceinline__ uint32_t smem_u32(const void* p) {
    uint32_t a;
    asm("{ .reg .u64 t; cvta.to.shared.u64 t, %1; cvt.u32.u64 %0, t; }" : "=r"(a) : "l"(p));
    return a;
}

// fp8(e4m3, RN, satfinite) of 4 scaled floats, packed into u32
__device__ __forceinline__ uint32_t q4(float4 v, float ratio) {
    __nv_fp8x2_storage_t lo =
        __nv_cvt_float2_to_fp8x2(make_float2(v.x * ratio, v.y * ratio), __NV_SATFINITE, __NV_E4M3);
    __nv_fp8x2_storage_t hi =
        __nv_cvt_float2_to_fp8x2(make_float2(v.z * ratio, v.w * ratio), __NV_SATFINITE, __NV_E4M3);
    return (uint32_t)lo | ((uint32_t)hi << 16);
}

__device__ __forceinline__ float max4(float4 v) {
    return fmaxf(fmaxf(fabsf(v.x), fabsf(v.y)), fmaxf(fabsf(v.z), fabsf(v.w)));
}

// ===================== quantization =====================
// One warp per (row, pair of 128-col tiles) — measured best (26.9us, 72% DRAM).
__global__ void quant_x_kernel(const float* __restrict__ x) {
    int gw   = (blockIdx.x * 256 + threadIdx.x) >> 5;
    int lane = threadIdx.x & 31;
    int row  = gw >> 4;             // 16 tile-pairs per row
    int kb2  = (gw & 15) << 1;      // first tile of the pair
    const float* p = x + (size_t)row * K_DIM + kb2 * 128 + lane * 4;
    const float4 v0 = *(const float4*)p;
    const float4 v1 = *(const float4*)(p + 128);
    float a0 = max4(v0);
    float a1 = max4(v1);
    #pragma unroll
    for (int o = 16; o > 0; o >>= 1) {
        a0 = fmaxf(a0, __shfl_xor_sync(0xffffffffu, a0, o));
        a1 = fmaxf(a1, __shfl_xor_sync(0xffffffffu, a1, o));
    }
    float safe0 = fmaxf(a0, 1e-4f);
    float safe1 = fmaxf(a1, 1e-4f);
    if (lane == 0) {
        g_sx[row * KBC + kb2]     = safe0 / 448.0f;
        g_sx[row * KBC + kb2 + 1] = safe1 / 448.0f;
    }
    uint8_t* q = g_qx + (size_t)row * K_DIM + kb2 * 128 + lane * 4;
    *(uint32_t*)q         = q4(v0, 448.0f / safe0);
    *(uint32_t*)(q + 128) = q4(v1, 448.0f / safe1);
}

// One CTA (512 threads) per 128x128 weight block, single pass: 8 float4 per
// thread held in registers across the block reduction (halved register
// pressure vs 256-thread variant -> better co-residency with quant_x in the
// stream-overlap window).
__global__ void __launch_bounds__(512) quant_w_kernel(const float* __restrict__ w) {
    int kb = blockIdx.x, nb = blockIdx.y;
    int tid = threadIdx.x;
    const float* base = w + (size_t)nb * 128 * K_DIM + (size_t)kb * 128;
    float4 v[8];
    float amax = 0.0f;
    #pragma unroll
    for (int i = 0; i < 8; i++) {
        int f = tid + i * 512;          // 0..4095 float4s
        int r = f >> 5, c = f & 31;
        v[i] = *(const float4*)(base + (size_t)r * K_DIM + c * 4);
        amax = fmaxf(amax, max4(v[i]));
    }
    #pragma unroll
    for (int o = 16; o > 0; o >>= 1)
        amax = fmaxf(amax, __shfl_xor_sync(0xffffffffu, amax, o));
    __shared__ float red[16];
    __shared__ float s_ratio;
    if ((tid & 31) == 0) red[tid >> 5] = amax;
    __syncthreads();
    if (tid == 0) {
        float a = red[0];
        #pragma unroll
        for (int i = 1; i < 16; i++) a = fmaxf(a, red[i]);
        float safe = fmaxf(a, 1e-6f);
        s_ratio = 448.0f / safe;
        g_sw[nb * KBC + kb] = safe / 448.0f;
    }
    __syncthreads();
    float ratio = s_ratio;
    uint8_t* qbase = g_qw + (size_t)nb * 128 * K_DIM + (size_t)kb * 128;
    #pragma unroll
    for (int i = 0; i < 8; i++) {
        int f = tid + i * 512;
        int r = f >> 5, c = f & 31;
        *(uint32_t*)(qbase + (size_t)r * K_DIM + c * 4) = q4(v[i], ratio);
    }
}

// ===================== GEMM (R5/R12 structure — measured best, do not perturb) ==
// 128x128 tile, 512 threads (16 warps, 4x4 grid of 32x32 warp tiles), 1 CTA/SM.
// fp8 rows padded to 144B (conflict-free ldmatrix). 4-stage cp.async pipeline.
static constexpr int ROW_BYTES   = 144;               // 128 data + 16 pad
static constexpr int TILE_BYTES  = 128 * ROW_BYTES;   // 18432
static constexpr int STAGE_BYTES = 2 * TILE_BYTES;    // 36864 (A + B)
static constexpr int NSTAGE      = 4;
static constexpr int SCALE_BYTES = 128 * KBC * 4 + 128;   // 16512
static constexpr int SMEM_TOTAL  = SCALE_BYTES + NSTAGE * STAGE_BYTES;  // 163968

__device__ __forceinline__ void load_stage(uint32_t stage_base, int stage, int kb,
                                           int m0, int n0, int tid) {
    const uint8_t* gA = g_qx + (size_t)m0 * K_DIM + kb * 128;
    const uint8_t* gB = g_qw + (size_t)n0 * K_DIM + kb * 128;
    uint32_t sa = stage_base + stage * STAGE_BYTES;
    uint32_t sb = sa + TILE_BYTES;
    #pragma unroll
    for (int i = 0; i < 2; i++) {
        int idx = tid + i * 512;            // 0..1023
        int r = idx >> 3, c = idx & 7;      // 128 rows x 8 chunks of 16B
        uint32_t so = r * ROW_BYTES + c * 16;
        const void* ga = gA + (size_t)r * K_DIM + c * 16;
        asm volatile("cp.async.cg.shared.global [%0], [%1], 16;" :: "r"(sa + so), "l"(ga));
        const void* gb = gB + (size_t)r * K_DIM + c * 16;
        asm volatile("cp.async.cg.shared.global [%0], [%1], 16;" :: "r"(sb + so), "l"(gb));
    }
}

__global__ void __launch_bounds__(512, 1) gemm_fp8_kernel(float* __restrict__ out) {
    extern __shared__ char smem[];
    uint32_t smem_base  = smem_u32(smem);
    uint32_t stage_base = smem_base + SCALE_BYTES;
    int tid  = threadIdx.x;
    int lane = tid & 31;
    int wid  = tid >> 5;
    int wm = wid & 3;                 // 4 warps along M  (32 rows each)
    int wn = wid >> 2;                // 4 warps along N  (32 cols each)
    int nb = blockIdx.x;
    int n0 = nb * 128;
    int m0 = blockIdx.y * 128;

    // prologue: start pipeline before anything else
    load_stage(stage_base, 0, 0, m0, n0, tid);
    asm volatile("cp.async.commit_group;" ::: "memory");
    load_stage(stage_base, 1, 1, m0, n0, tid);
    asm volatile("cp.async.commit_group;" ::: "memory");
    load_stage(stage_base, 2, 2, m0, n0, tid);
    asm volatile("cp.async.commit_group;" ::: "memory");

    // copy this CTA's scales into SMEM (contiguous 128*KBC floats) + KBC sw floats
    {
        const float4* src = (const float4*)(g_sx + (size_t)m0 * KBC);
        float4* dst = (float4*)smem;
        dst[tid]       = src[tid];
        dst[tid + 512] = src[tid + 512];
        if (tid < 8)
            ((float4*)(smem + 128 * KBC * 4))[tid] = ((const float4*)(g_sw + nb * KBC))[tid];
    }
    __syncthreads();

    float acc[2][4][4];
    #pragma unroll
    for (int i = 0; i < 2; i++)
        #pragma unroll
        for (int j = 0; j < 4; j++)
            #pragma unroll
            for (int q = 0; q < 4; q++) acc[i][j][q] = 0.0f;

    // ldmatrix lane offsets within a tile (b16 view of fp8 bytes)
    uint32_t a_off = (uint32_t)(wm * 32 + (lane & 15)) * ROW_BYTES + (lane >> 4) * 16;
    uint32_t b_off = (uint32_t)(wn * 32 + ((lane >> 4) << 3) + (lane & 7)) * ROW_BYTES
                   + (((lane >> 3) & 1) * 16);

    // in-SMEM scale addresses for this thread's accumulator rows
    int ra0 = wm * 32 + (lane >> 2);       // rows ra0, ra0+8, ra0+16, ra0+24
    const float* s_sx = (const float*)smem;
    const float* s_sw = (const float*)(smem + 128 * KBC * 4);

    #pragma unroll 1
    for (int kb = 0; kb < KBC; kb++) {
        asm volatile("cp.async.wait_group 2;" ::: "memory");
        __syncthreads();

        if (kb + 3 < KBC)
            load_stage(stage_base, (kb + 3) & (NSTAGE - 1), kb + 3, m0, n0, tid);
        asm volatile("cp.async.commit_group;" ::: "memory");

        // scales for this chunk
        float swv = s_sw[kb];
        float cs0[2], cs1[2];
        #pragma unroll
        for (int i = 0; i < 2; i++) {
            cs0[i] = s_sx[(ra0 + i * 16) * KBC + kb] * swv;
            cs1[i] = s_sx[(ra0 + i * 16 + 8) * KBC + kb] * swv;
        }

        uint32_t sa = stage_base + (kb & (NSTAGE - 1)) * STAGE_BYTES;
        uint32_t sb = sa + TILE_BYTES;

        float tmp[2][4][4];
        #pragma unroll
        for (int i = 0; i < 2; i++)
            #pragma unroll
            for (int j = 0; j < 4; j++)
                #pragma unroll
                for (int q = 0; q < 4; q++) tmp[i][j][q] = 0.0f;

        #pragma unroll
        for (int s = 0; s < 4; s++) {       // 4 k32 steps of 32 bytes
            uint32_t af[2][4];
            #pragma unroll
            for (int i = 0; i < 2; i++) {
                uint32_t addr = sa + a_off + (uint32_t)(i * 16 * ROW_BYTES + s * 32);
                asm volatile("ldmatrix.sync.aligned.m8n8.x4.shared.b16 {%0,%1,%2,%3}, [%4];"
                             : "=r"(af[i][0]), "=r"(af[i][1]), "=r"(af[i][2]), "=r"(af[i][3])
                             : "r"(addr));
            }
            uint32_t bf[8];                 // 4 n-tiles x 2 regs
            #pragma unroll
            for (int jp = 0; jp < 2; jp++) {
                uint32_t addr = sb + b_off + (uint32_t)(jp * 16 * ROW_BYTES + s * 32);
                asm volatile("ldmatrix.sync.aligned.m8n8.x4.shared.b16 {%0,%1,%2,%3}, [%4];"
                             : "=r"(bf[jp * 4 + 0]), "=r"(bf[jp * 4 + 1]),
                               "=r"(bf[jp * 4 + 2]), "=r"(bf[jp * 4 + 3])
                             : "r"(addr));
            }
            #pragma unroll
            for (int i = 0; i < 2; i++)
                #pragma unroll
                for (int j = 0; j < 4; j++) {
                    asm volatile(
                        "mma.sync.aligned.m16n8k32.row.col.f32.e4m3.e4m3.f32 "
                        "{%0,%1,%2,%3}, {%4,%5,%6,%7}, {%8,%9}, {%0,%1,%2,%3};"
                        : "+f"(tmp[i][j][0]), "+f"(tmp[i][j][1]),
                          "+f"(tmp[i][j][2]), "+f"(tmp[i][j][3])
                        : "r"(af[i][0]), "r"(af[i][1]), "r"(af[i][2]), "r"(af[i][3]),
                          "r"(bf[j * 2]), "r"(bf[j * 2 + 1]));
                }
        }

        #pragma unroll
        for (int i = 0; i < 2; i++)
            #pragma unroll
            for (int j = 0; j < 4; j++) {
                acc[i][j][0] = fmaf(cs0[i], tmp[i][j][0], acc[i][j][0]);
                acc[i][j][1] = fmaf(cs0[i], tmp[i][j][1], acc[i][j][1]);
                acc[i][j][2] = fmaf(cs1[i], tmp[i][j][2], acc[i][j][2]);
                acc[i][j][3] = fmaf(cs1[i], tmp[i][j][3], acc[i][j][3]);
            }
    }

    // epilogue
    #pragma unroll
    for (int i = 0; i < 2; i++) {
        int r0 = m0 + wm * 32 + i * 16 + (lane >> 2);
        #pragma unroll
        for (int j = 0; j < 4; j++) {
            int c = n0 + wn * 32 + j * 8 + 2 * (lane & 3);
            *(float2*)(out + (size_t)r0 * N_DIM + c)       = make_float2(acc[i][j][0], acc[i][j][1]);
            *(float2*)(out + (size_t)(r0 + 8) * N_DIM + c) = make_float2(acc[i][j][2], acc[i][j][3]);
        }
    }
}

// ===================== launch =====================
// quant_x and quant_w are independent: fork quant_w onto a side stream with
// the capture-legal event pattern so the two DRAM-bound kernels overlap;
// join before the GEMM.
extern "C" void kernel_launch(void* const* d_in, const int* in_sizes, int n_in,
                              void* d_out, int out_size) {
    const float* x = (const float*)d_in[0];
    const float* w = (const float*)d_in[1];
    float* out = (float*)d_out;

    static cudaStream_t s2 = nullptr;
    static cudaEvent_t ev_fork = nullptr, ev_join = nullptr;
    if (s2 == nullptr) {
        cudaStreamCreateWithFlags(&s2, cudaStreamNonBlocking);
        cudaEventCreateWithFlags(&ev_fork, cudaEventDisableTiming);
        cudaEventCreateWithFlags(&ev_join, cudaEventDisableTiming);
        cudaFuncSetAttribute(gemm_fp8_kernel,
                             cudaFuncAttributeMaxDynamicSharedMemorySize, SMEM_TOTAL);
    }

    // fork: side stream inherits the capture dependency
    cudaEventRecord(ev_fork, 0);
    cudaStreamWaitEvent(s2, ev_fork, 0);

    quant_w_kernel<<<dim3(KBC, NBC), 512, 0, s2>>>(w);   // side stream
    quant_x_kernel<<<(M_DIM * 16) / 8, 256>>>(x);        // main stream

    // join: GEMM waits on both
    cudaEventRecord(ev_join, s2);
    cudaStreamWaitEvent(0, ev_join, 0);

    gemm_fp8_kernel<<<dim3(N_DIM / 128, M_DIM / 128), 512, SMEM_TOTAL>>>(out);
}

// round 17
// speedup vs baseline: 1.0013x; 1.0013x over previous
#include <cuda_runtime.h>
#include <cuda_fp8.h>
#include <cuda_fp16.h>
#include <cstdint>
#include <cstring>

// ===================== problem constants =====================
#define M_DIM 8192
#define K_DIM 4096
#define N_DIM 4096
#define KBC   (K_DIM / 128)              // 32 K-chunks of 128
#define NBC   (N_DIM / 128)              // 32 weight-block columns

// ===================== scratch (device globals, no malloc) =====================
__device__ uint8_t g_qx[(size_t)M_DIM * K_DIM];   // fp8 e4m3 activations
__device__ float   g_sx[M_DIM * KBC];             // act scales [M, K/128]
__device__ uint8_t g_qw[(size_t)N_DIM * K_DIM];   // fp8 e4m3 weights
__device__ float   g_sw[NBC * KBC];               // weight scales [N/128, K/128]

// ===================== helpers =====================
__device__ __forceinline__ uint32_t smem_u32(const void* p) {
    uint32_t a;
    asm("{ .reg .u64 t; cvta.to.shared.u64 t, %1; cvt.u32.u64 %0, t; }" : "=r"(a) : "l"(p));
    return a;
}

// fp8(e4m3, RN, satfinite) of 4 scaled floats, packed into u32
__device__ __forceinline__ uint32_t q4(float4 v, float ratio) {
    __nv_fp8x2_storage_t lo =
        __nv_cvt_float2_to_fp8x2(make_float2(v.x * ratio, v.y * ratio), __NV_SATFINITE, __NV_E4M3);
    __nv_fp8x2_storage_t hi =
        __nv_cvt_float2_to_fp8x2(make_float2(v.z * ratio, v.w * ratio), __NV_SATFINITE, __NV_E4M3);
    return (uint32_t)lo | ((uint32_t)hi << 16);
}

__device__ __forceinline__ float max4(float4 v) {
    return fmaxf(fmaxf(fabsf(v.x), fabsf(v.y)), fmaxf(fabsf(v.z), fabsf(v.w)));
}

// ===================== quantization =====================
// One warp per (row, pair of 128-col tiles) — measured best (26.9us, 72% DRAM).
__global__ void quant_x_kernel(const float* __restrict__ x) {
    int gw   = (blockIdx.x * 256 + threadIdx.x) >> 5;
    int lane = threadIdx.x & 31;
    int row  = gw >> 4;             // 16 tile-pairs per row
    int kb2  = (gw & 15) << 1;      // first tile of the pair
    const float* p = x + (size_t)row * K_DIM + kb2 * 128 + lane * 4;
    const float4 v0 = *(const float4*)p;
    const float4 v1 = *(const float4*)(p + 128);
    float a0 = max4(v0);
    float a1 = max4(v1);
    #pragma unroll
    for (int o = 16; o > 0; o >>= 1) {
        a0 = fmaxf(a0, __shfl_xor_sync(0xffffffffu, a0, o));
        a1 = fmaxf(a1, __shfl_xor_sync(0xffffffffu, a1, o));
    }
    float safe0 = fmaxf(a0, 1e-4f);
    float safe1 = fmaxf(a1, 1e-4f);
    if (lane == 0) {
        g_sx[row * KBC + kb2]     = safe0 / 448.0f;
        g_sx[row * KBC + kb2 + 1] = safe1 / 448.0f;
    }
    uint8_t* q = g_qx + (size_t)row * K_DIM + kb2 * 128 + lane * 4;
    *(uint32_t*)q         = q4(v0, 448.0f / safe0);
    *(uint32_t*)(q + 128) = q4(v1, 448.0f / safe1);
}

// One CTA (256 threads) per 128x128 weight block, single pass: 16 float4 per
// thread held in registers across the block reduction (no second global read).
// This exact variant was in the 893.0us best total (R15).
__global__ void quant_w_kernel(const float* __restrict__ w) {
    int kb = blockIdx.x, nb = blockIdx.y;
    int tid = threadIdx.x;
    const float* base = w + (size_t)nb * 128 * K_DIM + (size_t)kb * 128;
    float4 v[16];
    float amax = 0.0f;
    #pragma unroll
    for (int i = 0; i < 16; i++) {
        int f = tid + i * 256;          // 0..4095 float4s
        int r = f >> 5, c = f & 31;
        v[i] = *(const float4*)(base + (size_t)r * K_DIM + c * 4);
        amax = fmaxf(amax, max4(v[i]));
    }
    #pragma unroll
    for (int o = 16; o > 0; o >>= 1)
        amax = fmaxf(amax, __shfl_xor_sync(0xffffffffu, amax, o));
    __shared__ float red[8];
    __shared__ float s_ratio;
    if ((tid & 31) == 0) red[tid >> 5] = amax;
    __syncthreads();
    if (tid == 0) {
        float a = red[0];
        #pragma unroll
        for (int i = 1; i < 8; i++) a = fmaxf(a, red[i]);
        float safe = fmaxf(a, 1e-6f);
        s_ratio = 448.0f / safe;
        g_sw[nb * KBC + kb] = safe / 448.0f;
    }
    __syncthreads();
    float ratio = s_ratio;
    uint8_t* qbase = g_qw + (size_t)nb * 128 * K_DIM + (size_t)kb * 128;
    #pragma unroll
    for (int i = 0; i < 16; i++) {
        int f = tid + i * 256;
        int r = f >> 5, c = f & 31;
        *(uint32_t*)(qbase + (size_t)r * K_DIM + c * 4) = q4(v[i], ratio);
    }
}

// ===================== GEMM (R5/R12 structure — measured best, do not perturb) ==
// 128x128 tile, 512 threads (16 warps, 4x4 grid of 32x32 warp tiles), 1 CTA/SM.
// fp8 rows padded to 144B (conflict-free ldmatrix). 4-stage cp.async pipeline.
static constexpr int ROW_BYTES   = 144;               // 128 data + 16 pad
static constexpr int TILE_BYTES  = 128 * ROW_BYTES;   // 18432
static constexpr int STAGE_BYTES = 2 * TILE_BYTES;    // 36864 (A + B)
static constexpr int NSTAGE      = 4;
static constexpr int SCALE_BYTES = 128 * KBC * 4 + 128;   // 16512
static constexpr int SMEM_TOTAL  = SCALE_BYTES + NSTAGE * STAGE_BYTES;  // 163968

__device__ __forceinline__ void load_stage(uint32_t stage_base, int stage, int kb,
                                           int m0, int n0, int tid) {
    const uint8_t* gA = g_qx + (size_t)m0 * K_DIM + kb * 128;
    const uint8_t* gB = g_qw + (size_t)n0 * K_DIM + kb * 128;
    uint32_t sa = stage_base + stage * STAGE_BYTES;
    uint32_t sb = sa + TILE_BYTES;
    #pragma unroll
    for (int i = 0; i < 2; i++) {
        int idx = tid + i * 512;            // 0..1023
        int r = idx >> 3, c = idx & 7;      // 128 rows x 8 chunks of 16B
        uint32_t so = r * ROW_BYTES + c * 16;
        const void* ga = gA + (size_t)r * K_DIM + c * 16;
        asm volatile("cp.async.cg.shared.global [%0], [%1], 16;" :: "r"(sa + so), "l"(ga));
        const void* gb = gB + (size_t)r * K_DIM + c * 16;
        asm volatile("cp.async.cg.shared.global [%0], [%1], 16;" :: "r"(sb + so), "l"(gb));
    }
}

__global__ void __launch_bounds__(512, 1) gemm_fp8_kernel(float* __restrict__ out) {
    extern __shared__ char smem[];
    uint32_t smem_base  = smem_u32(smem);
    uint32_t stage_base = smem_base + SCALE_BYTES;
    int tid  = threadIdx.x;
    int lane = tid & 31;
    int wid  = tid >> 5;
    int wm = wid & 3;                 // 4 warps along M  (32 rows each)
    int wn = wid >> 2;                // 4 warps along N  (32 cols each)
    int nb = blockIdx.x;
    int n0 = nb * 128;
    int m0 = blockIdx.y * 128;

    // prologue: start pipeline before anything else
    load_stage(stage_base, 0, 0, m0, n0, tid);
    asm volatile("cp.async.commit_group;" ::: "memory");
    load_stage(stage_base, 1, 1, m0, n0, tid);
    asm volatile("cp.async.commit_group;" ::: "memory");
    load_stage(stage_base, 2, 2, m0, n0, tid);
    asm volatile("cp.async.commit_group;" ::: "memory");

    // copy this CTA's scales into SMEM (contiguous 128*KBC floats) + KBC sw floats
    {
        const float4* src = (const float4*)(g_sx + (size_t)m0 * KBC);
        float4* dst = (float4*)smem;
        dst[tid]       = src[tid];
        dst[tid + 512] = src[tid + 512];
        if (tid < 8)
            ((float4*)(smem + 128 * KBC * 4))[tid] = ((const float4*)(g_sw + nb * KBC))[tid];
    }
    __syncthreads();

    float acc[2][4][4];
    #pragma unroll
    for (int i = 0; i < 2; i++)
        #pragma unroll
        for (int j = 0; j < 4; j++)
            #pragma unroll
            for (int q = 0; q < 4; q++) acc[i][j][q] = 0.0f;

    // ldmatrix lane offsets within a tile (b16 view of fp8 bytes)
    uint32_t a_off = (uint32_t)(wm * 32 + (lane & 15)) * ROW_BYTES + (lane >> 4) * 16;
    uint32_t b_off = (uint32_t)(wn * 32 + ((lane >> 4) << 3) + (lane & 7)) * ROW_BYTES
                   + (((lane >> 3) & 1) * 16);

    // in-SMEM scale addresses for this thread's accumulator rows
    int ra0 = wm * 32 + (lane >> 2);       // rows ra0, ra0+8, ra0+16, ra0+24
    const float* s_sx = (const float*)smem;
    const float* s_sw = (const float*)(smem + 128 * KBC * 4);

    #pragma unroll 1
    for (int kb = 0; kb < KBC; kb++) {
        asm volatile("cp.async.wait_group 2;" ::: "memory");
        __syncthreads();

        if (kb + 3 < KBC)
            load_stage(stage_base, (kb + 3) & (NSTAGE - 1), kb + 3, m0, n0, tid);
        asm volatile("cp.async.commit_group;" ::: "memory");

        // scales for this chunk
        float swv = s_sw[kb];
        float cs0[2], cs1[2];
        #pragma unroll
        for (int i = 0; i < 2; i++) {
            cs0[i] = s_sx[(ra0 + i * 16) * KBC + kb] * swv;
            cs1[i] = s_sx[(ra0 + i * 16 + 8) * KBC + kb] * swv;
        }

        uint32_t sa = stage_base + (kb & (NSTAGE - 1)) * STAGE_BYTES;
        uint32_t sb = sa + TILE_BYTES;

        float tmp[2][4][4];
        #pragma unroll
        for (int i = 0; i < 2; i++)
            #pragma unroll
            for (int j = 0; j < 4; j++)
                #pragma unroll
                for (int q = 0; q < 4; q++) tmp[i][j][q] = 0.0f;

        #pragma unroll
        for (int s = 0; s < 4; s++) {       // 4 k32 steps of 32 bytes
            uint32_t af[2][4];
            #pragma unroll
            for (int i = 0; i < 2; i++) {
                uint32_t addr = sa + a_off + (uint32_t)(i * 16 * ROW_BYTES + s * 32);
                asm volatile("ldmatrix.sync.aligned.m8n8.x4.shared.b16 {%0,%1,%2,%3}, [%4];"
                             : "=r"(af[i][0]), "=r"(af[i][1]), "=r"(af[i][2]), "=r"(af[i][3])
                             : "r"(addr));
            }
            uint32_t bf[8];                 // 4 n-tiles x 2 regs
            #pragma unroll
            for (int jp = 0; jp < 2; jp++) {
                uint32_t addr = sb + b_off + (uint32_t)(jp * 16 * ROW_BYTES + s * 32);
                asm volatile("ldmatrix.sync.aligned.m8n8.x4.shared.b16 {%0,%1,%2,%3}, [%4];"
                             : "=r"(bf[jp * 4 + 0]), "=r"(bf[jp * 4 + 1]),
                               "=r"(bf[jp * 4 + 2]), "=r"(bf[jp * 4 + 3])
                             : "r"(addr));
            }
            #pragma unroll
            for (int i = 0; i < 2; i++)
                #pragma unroll
                for (int j = 0; j < 4; j++) {
                    asm volatile(
                        "mma.sync.aligned.m16n8k32.row.col.f32.e4m3.e4m3.f32 "
                        "{%0,%1,%2,%3}, {%4,%5,%6,%7}, {%8,%9}, {%0,%1,%2,%3};"
                        : "+f"(tmp[i][j][0]), "+f"(tmp[i][j][1]),
                          "+f"(tmp[i][j][2]), "+f"(tmp[i][j][3])
                        : "r"(af[i][0]), "r"(af[i][1]), "r"(af[i][2]), "r"(af[i][3]),
                          "r"(bf[j * 2]), "r"(bf[j * 2 + 1]));
                }
        }

        #pragma unroll
        for (int i = 0; i < 2; i++)
            #pragma unroll
            for (int j = 0; j < 4; j++) {
                acc[i][j][0] = fmaf(cs0[i], tmp[i][j][0], acc[i][j][0]);
                acc[i][j][1] = fmaf(cs0[i], tmp[i][j][1], acc[i][j][1]);
                acc[i][j][2] = fmaf(cs1[i], tmp[i][j][2], acc[i][j][2]);
                acc[i][j][3] = fmaf(cs1[i], tmp[i][j][3], acc[i][j][3]);
            }
    }

    // epilogue
    #pragma unroll
    for (int i = 0; i < 2; i++) {
        int r0 = m0 + wm * 32 + i * 16 + (lane >> 2);
        #pragma unroll
        for (int j = 0; j < 4; j++) {
            int c = n0 + wn * 32 + j * 8 + 2 * (lane & 3);
            *(float2*)(out + (size_t)r0 * N_DIM + c)       = make_float2(acc[i][j][0], acc[i][j][1]);
            *(float2*)(out + (size_t)(r0 + 8) * N_DIM + c) = make_float2(acc[i][j][2], acc[i][j][3]);
        }
    }
}

// ===================== launch =====================
// quant_x and quant_w are independent: fork quant_w onto a side stream with
// the capture-legal event pattern so the two DRAM-bound kernels overlap;
// join before the GEMM. (Measured: part of the 893.0us best.)
extern "C" void kernel_launch(void* const* d_in, const int* in_sizes, int n_in,
                              void* d_out, int out_size) {
    const float* x = (const float*)d_in[0];
    const float* w = (const float*)d_in[1];
    float* out = (float*)d_out;

    static cudaStream_t s2 = nullptr;
    static cudaEvent_t ev_fork = nullptr, ev_join = nullptr;
    if (s2 == nullptr) {
        cudaStreamCreateWithFlags(&s2, cudaStreamNonBlocking);
        cudaEventCreateWithFlags(&ev_fork, cudaEventDisableTiming);
        cudaEventCreateWithFlags(&ev_join, cudaEventDisableTiming);
        cudaFuncSetAttribute(gemm_fp8_kernel,
                             cudaFuncAttributeMaxDynamicSharedMemorySize, SMEM_TOTAL);
    }

    // fork: side stream inherits the capture dependency
    cudaEventRecord(ev_fork, 0);
    cudaStreamWaitEvent(s2, ev_fork, 0);

    quant_w_kernel<<<dim3(KBC, NBC), 256, 0, s2>>>(w);   // side stream
    quant_x_kernel<<<(M_DIM * 16) / 8, 256>>>(x);        // main stream

    // join: GEMM waits on both
    cudaEventRecord(ev_join, s2);
    cudaStreamWaitEvent(0, ev_join, 0);

    gemm_fp8_kernel<<<dim3(N_DIM / 128, M_DIM / 128), 512, SMEM_TOTAL>>>(out);
}